// round 17
// baseline (speedup 1.0000x reference)
#include <cuda_runtime.h>
#include <cuda_bf16.h>
#include <math.h>
#include <stdint.h>

// Problem constants
#define H   1024
#define IW  512          // moe_intermediate_size
#define E   16
#define T   4096         // B*S tokens
#define P   8192         // T * K pairs
#define ISH 1024         // shared intermediate (I * 2)

// tcgen05 available only on the compute_103a/100a device pass.
#if defined(__CUDA_ARCH__)
#if defined(__CUDA_ARCH_FEAT_SM103_ALL) || defined(__CUDA_ARCH_FEAT_SM100_ALL) || \
    (defined(__CUDA_ARCH_SPECIFIC__) && (__CUDA_ARCH_SPECIFIC__ >= 1000))
#define USE_TCGEN05 1
#else
#define USE_TCGEN05 0
#endif
#else
#define USE_TCGEN05 0
#endif

// ---------------- device scratch ----------------
__device__ int   g_tc_ok;
__device__ int   g_count[16];
__device__ int   g_offsets[17];
__device__ int   g_cursor[16];
__device__ int   g_topk_idx[T * 2];
__device__ float g_topk_w[T * 2];
__device__ int   g_pair_token[P];
__device__ int   g_pos_of[T * 2];
__device__ float g_act[(size_t)P * 512];    // routed silu(gate)*up
__device__ float g_down[(size_t)P * 1024];  // routed down output (unscaled)
__device__ float g_sact[(size_t)T * 1024];  // shared silu(gate)*up

__device__ __forceinline__ uint32_t f2tf(float f) {
    uint32_t r; asm("cvt.rna.tf32.f32 %0, %1;" : "=r"(r) : "f"(f)); return r;
}
__device__ __forceinline__ float silu_mul(float g, float u) {
    return g / (1.f + expf(-g)) * u;
}

// ---------------- routing (unchanged, passing) ----------------
__global__ void k_init() {
    int i = threadIdx.x;
    if (i < 16) g_count[i] = 0;
}

__global__ void k_router(const float* __restrict__ x,
                         const float* __restrict__ rw) {
    int t = blockIdx.x;
    __shared__ float xs[H];
    __shared__ float sc[16];
    int tid = threadIdx.x;
    const float4* xv = (const float4*)(x + (size_t)t * H);
    ((float4*)xs)[tid]       = xv[tid];
    ((float4*)xs)[tid + 128] = xv[tid + 128];
    __syncthreads();

    int e = tid >> 3, lane = tid & 7;
    const float* w = rw + (size_t)e * H;
    float s = 0.f;
    #pragma unroll 4
    for (int h = lane * 4; h < H; h += 32) {
        float4 a = *(const float4*)(xs + h);
        float4 b = *(const float4*)(w + h);
        s += a.x * b.x + a.y * b.y + a.z * b.z + a.w * b.w;
    }
    #pragma unroll
    for (int o = 4; o; o >>= 1) s += __shfl_down_sync(0xffffffffu, s, o, 8);
    if (lane == 0) sc[e] = s;
    __syncthreads();

    if (tid == 0) {
        int i1 = 0; float s1 = sc[0];
        #pragma unroll
        for (int i = 1; i < 16; i++) if (sc[i] > s1) { s1 = sc[i]; i1 = i; }
        int i2 = -1; float s2 = -3.0e38f;
        #pragma unroll
        for (int i = 0; i < 16; i++) if (i != i1 && sc[i] > s2) { s2 = sc[i]; i2 = i; }
        float r  = expf(s2 - s1);
        float w1 = 1.f / (1.f + r);
        float w2 = r / (1.f + r);
        g_topk_idx[t * 2]     = i1;
        g_topk_idx[t * 2 + 1] = i2;
        g_topk_w[t * 2]       = w1;
        g_topk_w[t * 2 + 1]   = w2;
        atomicAdd(&g_count[i1], 1);
        atomicAdd(&g_count[i2], 1);
    }
}

__global__ void k_scan() {
    if (threadIdx.x == 0) {
        int o = 0;
        for (int e = 0; e < 16; e++) { g_offsets[e] = o; o += g_count[e]; }
        g_offsets[16] = o;
    }
    if (threadIdx.x < 16) g_cursor[threadIdx.x] = 0;
}

__global__ void k_scatter() {
    int t = blockIdx.x * blockDim.x + threadIdx.x;
    if (t >= T) return;
    #pragma unroll
    for (int s = 0; s < 2; s++) {
        int e   = g_topk_idx[t * 2 + s];
        int pos = g_offsets[e] + atomicAdd(&g_cursor[e], 1);
        g_pair_token[pos]   = t;
        g_pos_of[t * 2 + s] = pos;
    }
}

#define SMEM_BYTES 51200

#if USE_TCGEN05
// =====================================================================
// tcgen05 tf32 SS helpers — instruction forms exactly as R15 (proven to
// execute without trap). Layout: BOTH operands K-major SW128 (verified
// by test_mma_iter / test_mma_mxf8_ss).
// =====================================================================
__device__ __forceinline__ uint32_t smem_u32(const void* p) {
    uint32_t a;
    asm("{ .reg .u64 t; cvta.to.shared.u64 t, %1; cvt.u32.u64 %0, t; }" : "=r"(a) : "l"(p));
    return a;
}
__device__ __forceinline__ uint32_t elect_one() {
    uint32_t pred;
    asm volatile("{\n\t.reg .pred p;\n\telect.sync _|p, 0xFFFFFFFF;\n\tselp.b32 %0, 1, 0, p;\n\t}" : "=r"(pred));
    return pred;
}
#define SW128(b) ((b) ^ (((b) >> 3) & 0x70))

__device__ __forceinline__ uint64_t desc_k(uint32_t addr) {   // K-major SW128: LBO=1, SBO=64
    return ((uint64_t)2 << 61) | ((uint64_t)1 << 46) | ((uint64_t)64 << 32) |
           ((uint64_t)1 << 16) | ((uint64_t)(addr >> 4) & 0x3FFF);
}

__device__ __forceinline__ void tcgen05_alloc(uint32_t smem_dst, uint32_t ncols) {
    asm volatile("tcgen05.alloc.cta_group::1.sync.aligned.shared::cta.b32 [%0], %1;"
                 :: "r"(smem_dst), "r"(ncols) : "memory");
}
__device__ __forceinline__ void tcgen05_dealloc(uint32_t tmem, uint32_t ncols) {
    asm volatile("tcgen05.dealloc.cta_group::1.sync.aligned.b32 %0, %1;" :: "r"(tmem), "r"(ncols));
}
__device__ __forceinline__ void mma_tf32(uint32_t d, uint64_t ad, uint64_t bd, uint32_t idesc, uint32_t en) {
    asm volatile("{\n\t.reg .pred p;\n\tsetp.ne.u32 p, %4, 0;\n\t"
                 "tcgen05.mma.cta_group::1.kind::tf32 [%0], %1, %2, %3, p;\n\t}"
                 :: "r"(d), "l"(ad), "l"(bd), "r"(idesc), "r"(en) : "memory");
}
__device__ __forceinline__ void tcgen05_commit(uint32_t mbar) {
    asm volatile("tcgen05.commit.cta_group::1.mbarrier::arrive::one.shared::cluster.b64 [%0];"
                 :: "r"(mbar) : "memory");
}
#define MBAR_INIT(a, c) \
    asm volatile("mbarrier.init.shared.b64 [%0], %1;" :: "r"(a), "r"(c) : "memory")
#define MBAR_INVAL(a) \
    asm volatile("mbarrier.inval.shared.b64 [%0];" :: "r"(a) : "memory")
#define MBAR_WAIT(a, ph) do {                                                   \
    uint32_t _m = (a), _p = (ph), _d;                                           \
    asm volatile("{\n\t.reg .pred p;\n\t"                                       \
        "mbarrier.try_wait.parity.acquire.cta.shared::cta.b64 p, [%1], %2;\n\t" \
        "selp.b32 %0, 1, 0, p;\n\t}" : "=r"(_d) : "r"(_m), "r"(_p) : "memory"); \
    if (!_d) {                                                                  \
        asm volatile("{\n\t.reg .pred P1;\n\t"                                  \
            "WL_%=:\n\t"                                                        \
            "mbarrier.try_wait.parity.acquire.cta.shared::cta.b64 P1, [%0], %1, 0x989680;\n\t" \
            "@P1 bra.uni WD_%=;\n\t"                                            \
            "bra.uni WL_%=;\n\t"                                                \
            "WD_%=:\n\t}" :: "r"(_m), "r"(_p) : "memory");                      \
    }                                                                           \
} while (0)
#define TC_LD_X32(r, a)                                                         \
    asm volatile("tcgen05.ld.sync.aligned.32x32b.x32.b32 "                      \
        "{%0,%1,%2,%3,%4,%5,%6,%7,%8,%9,%10,%11,%12,%13,%14,%15,"              \
        "%16,%17,%18,%19,%20,%21,%22,%23,%24,%25,%26,%27,%28,%29,%30,%31}, [%32];" \
        : "=r"((r)[0]),"=r"((r)[1]),"=r"((r)[2]),"=r"((r)[3]),                  \
          "=r"((r)[4]),"=r"((r)[5]),"=r"((r)[6]),"=r"((r)[7]),                  \
          "=r"((r)[8]),"=r"((r)[9]),"=r"((r)[10]),"=r"((r)[11]),                \
          "=r"((r)[12]),"=r"((r)[13]),"=r"((r)[14]),"=r"((r)[15]),              \
          "=r"((r)[16]),"=r"((r)[17]),"=r"((r)[18]),"=r"((r)[19]),              \
          "=r"((r)[20]),"=r"((r)[21]),"=r"((r)[22]),"=r"((r)[23]),              \
          "=r"((r)[24]),"=r"((r)[25]),"=r"((r)[26]),"=r"((r)[27]),              \
          "=r"((r)[28]),"=r"((r)[29]),"=r"((r)[30]),"=r"((r)[31])               \
        : "r"(a))
#define TC_WAIT_LD()  asm volatile("tcgen05.wait::ld.sync.aligned;" ::: "memory")
#define TC_FENCE_AFTER()  asm volatile("tcgen05.fence::after_thread_sync;" ::: "memory")
#define TC_FENCE_BEFORE() asm volatile("tcgen05.fence::before_thread_sync;" ::: "memory")
#define FENCE_ASYNC() asm volatile("fence.proxy.async.shared::cta;" ::: "memory")

// idesc: dtype F32 (1<<4), atype/btype TF32 (2<<7, 2<<10), N=32 (4<<17),
// M=128 (8<<24). K-major A and B. Field placement matches the verified
// f16 constant 0x8080490 (which decodes as dtype=1, a/b=BF16=1, N=32, M=128).
#define IDESC_TF32 ((1u << 4) | (2u << 7) | (2u << 10) | (4u << 17) | (8u << 24))

template<bool FUSED>
__device__ __forceinline__ void tc_gemm(
    const float* __restrict__ A, int lda,
    const int* __restrict__ rowmap, int row_off, int Mrem,
    const float* __restrict__ B0, const float* __restrict__ B1, int ldb, int nbase,
    float* __restrict__ C, int ldc, int K)
{
    extern __shared__ char dsm[];
    uint32_t raw = smem_u32(dsm);
    uint32_t sb  = (raw + 1023) & ~1023u;
    char* dbase  = dsm + (sb - raw);
    uint32_t ctrl = sb;                       // [0]=tmem ptr, [8],[16]=mbarriers
    uint32_t Abuf = sb + 1024;                // + s*16384
    uint32_t Bbuf = sb + 1024 + 32768;        // + s*8192 + j*4096

    int tid = threadIdx.x, wid = tid >> 5, lid = tid & 31;

    if (wid == 0) tcgen05_alloc(ctrl, 64);
    if (tid == 0) { MBAR_INIT(ctrl + 8, 1); MBAR_INIT(ctrl + 16, 1); }
    __syncthreads();
    uint32_t tmem;
    asm volatile("ld.shared.b32 %0, [%1];" : "=r"(tmem) : "r"(ctrl));

    // A loader: 4 rows/thread, 4 k-cols each (float4), K-major SW128
    int arow = tid >> 3;
    int kcol = (tid & 7) * 4;
    const float* ap[4];
    uint32_t sA[4];
    #pragma unroll
    for (int i = 0; i < 4; i++) {
        int r = arow + i * 32;
        ap[i] = nullptr;
        if (r < Mrem) {
            int rr = rowmap ? rowmap[row_off + r] : (row_off + r);
            ap[i] = A + (size_t)rr * lda + kcol;
        }
        sA[i] = (uint32_t)(r >> 3) * 1024u + SW128((uint32_t)((r & 7) * 128 + kcol * 4));
    }
    // B loader (transpose to K-major): thread -> n-row = tid&31, k-group = tid>>5.
    int bn = tid & 31;
    int kq = tid >> 5;        // 0..7, covers k = kq*4 .. kq*4+3 within chunk
    const float* bgp[2];
    bgp[0] = B0 + nbase + bn;
    bgp[1] = FUSED ? (B1 + nbase + bn) : (B0 + nbase + 32 + bn);
    uint32_t sB = (uint32_t)(bn >> 3) * 1024u + SW128((uint32_t)((bn & 7) * 128 + kq * 16));

    int ph0 = 0, ph1 = 0;
    const int niter = K / 32;
    for (int it = 0; it < niter; it++) {
        int s = it & 1;
        if (it >= 2) {
            if (s == 0) { MBAR_WAIT(ctrl + 8,  ph0); ph0 ^= 1; }
            else        { MBAR_WAIT(ctrl + 16, ph1); ph1 ^= 1; }
        }
        int k0 = it * 32;
        char* abuf = dbase + 1024 + s * 16384;
        char* bbuf = dbase + 1024 + 32768 + s * 8192;
        #pragma unroll
        for (int i = 0; i < 4; i++) {
            float4 v = ap[i] ? *(const float4*)(ap[i] + k0) : make_float4(0.f, 0.f, 0.f, 0.f);
            uint4 u; u.x = f2tf(v.x); u.y = f2tf(v.y); u.z = f2tf(v.z); u.w = f2tf(v.w);
            *(uint4*)(abuf + sA[i]) = u;
        }
        #pragma unroll
        for (int j = 0; j < 2; j++) {
            const float* g0 = bgp[j] + (size_t)(k0 + kq * 4) * ldb;
            uint4 u;
            u.x = f2tf(g0[0]);
            u.y = f2tf(g0[(size_t)ldb]);
            u.z = f2tf(g0[(size_t)2 * ldb]);
            u.w = f2tf(g0[(size_t)3 * ldb]);
            *(uint4*)(bbuf + j * 4096 + sB) = u;
        }
        FENCE_ASYNC();
        __syncthreads();
        if (wid == 0 && elect_one()) {
            TC_FENCE_AFTER();
            uint64_t ad  = desc_k(Abuf + (uint32_t)s * 16384u);
            uint64_t bd0 = desc_k(Bbuf + (uint32_t)s * 8192u);
            uint64_t bd1 = desc_k(Bbuf + (uint32_t)s * 8192u + 4096u);
            #pragma unroll
            for (int st = 0; st < 4; st++) {
                uint32_t en = (it > 0 || st > 0) ? 1u : 0u;
                mma_tf32(tmem,      ad + st * 2, bd0 + st * 2, IDESC_TF32, en);
                mma_tf32(tmem + 32, ad + st * 2, bd1 + st * 2, IDESC_TF32, en);
            }
            tcgen05_commit(ctrl + 8 + s * 8);
        }
    }

    MBAR_WAIT(ctrl + 8,  ph0);
    MBAR_WAIT(ctrl + 16, ph1);
    TC_FENCE_AFTER();

    if (wid < 4) {
        uint32_t d0[32], d1[32];
        TC_LD_X32(d0, tmem);
        TC_LD_X32(d1, tmem + 32);
        TC_WAIT_LD();
        TC_FENCE_BEFORE();
        int row = wid * 32 + lid;
        if (row < Mrem) {
            float* cp = C + (size_t)row * ldc + nbase;
            if (FUSED) {
                #pragma unroll
                for (int c = 0; c < 32; c += 4) {
                    float4 o;
                    o.x = silu_mul(__uint_as_float(d0[c + 0]), __uint_as_float(d1[c + 0]));
                    o.y = silu_mul(__uint_as_float(d0[c + 1]), __uint_as_float(d1[c + 1]));
                    o.z = silu_mul(__uint_as_float(d0[c + 2]), __uint_as_float(d1[c + 2]));
                    o.w = silu_mul(__uint_as_float(d0[c + 3]), __uint_as_float(d1[c + 3]));
                    *(float4*)(cp + c) = o;
                }
            } else {
                #pragma unroll
                for (int c = 0; c < 32; c += 4) {
                    *(float4*)(cp + c) = make_float4(
                        __uint_as_float(d0[c + 0]), __uint_as_float(d0[c + 1]),
                        __uint_as_float(d0[c + 2]), __uint_as_float(d0[c + 3]));
                    *(float4*)(cp + 32 + c) = make_float4(
                        __uint_as_float(d1[c + 0]), __uint_as_float(d1[c + 1]),
                        __uint_as_float(d1[c + 2]), __uint_as_float(d1[c + 3]));
                }
            }
        }
    }
    __syncthreads();
    if (tid == 0) { MBAR_INVAL(ctrl + 8); MBAR_INVAL(ctrl + 16); }
    __syncthreads();
    if (wid == 0) tcgen05_dealloc(tmem, 64);
}
#endif  // USE_TCGEN05

// =====================================================================
// Probe: one-CTA 128x32x32 tf32 tcgen05 GEMM on exact values, checked
// against an in-kernel FFMA reference. Sets g_tc_ok.
// =====================================================================
__global__ void k_tc_probe() {
#if USE_TCGEN05
    __shared__ char praw[16384 + 4096 + 1024];
    __shared__ uint64_t pctrl[4];     // [0]=tmem ptr (b32), [1]=mbarrier
    __shared__ int perr;
    int tid = threadIdx.x, wid = tid >> 5, lid = tid & 31;
    uint32_t rawa = smem_u32(praw);
    uint32_t ab   = (rawa + 1023) & ~1023u;
    char* pb      = praw + (ab - rawa);
    uint32_t bb   = ab + 16384;
    uint32_t cb   = smem_u32(pctrl);

    if (tid == 0) perr = 0;
    for (int idx = tid; idx < 128 * 32; idx += 256) {
        int m = idx >> 5, k = idx & 31;
        float v = (float)((m * 3 + k) % 8) * 0.25f - 1.0f;
        uint32_t off = (uint32_t)(m >> 3) * 1024u + SW128((uint32_t)((m & 7) * 128 + k * 4));
        *(uint32_t*)(pb + off) = f2tf(v);
    }
    for (int idx = tid; idx < 32 * 32; idx += 256) {
        int n = idx >> 5, k = idx & 31;
        float v = (float)((n + 2 * k) % 8) * 0.25f - 0.75f;
        uint32_t off = (uint32_t)(n >> 3) * 1024u + SW128((uint32_t)((n & 7) * 128 + k * 4));
        *(uint32_t*)(pb + 16384 + off) = f2tf(v);
    }
    if (wid == 0) tcgen05_alloc(cb, 64);
    if (tid == 0) MBAR_INIT(cb + 8, 1);
    FENCE_ASYNC();
    __syncthreads();
    uint32_t tmem;
    asm volatile("ld.shared.b32 %0, [%1];" : "=r"(tmem) : "r"(cb));

    if (wid == 0 && elect_one()) {
        TC_FENCE_AFTER();
        uint64_t ad = desc_k(ab), bd = desc_k(bb);
        #pragma unroll
        for (int st = 0; st < 4; st++)
            mma_tf32(tmem, ad + st * 2, bd + st * 2, IDESC_TF32, st > 0 ? 1u : 0u);
        tcgen05_commit(cb + 8);
    }
    __syncthreads();
    MBAR_WAIT(cb + 8, 0);
    TC_FENCE_AFTER();

    if (wid < 4) {
        uint32_t d[32];
        TC_LD_X32(d, tmem);
        TC_WAIT_LD();
        TC_FENCE_BEFORE();
        int m = wid * 32 + lid;
        int bad = 0;
        for (int n = 0; n < 32; n++) {
            float ref = 0.f;
            for (int k = 0; k < 32; k++)
                ref += ((float)((m * 3 + k) % 8) * 0.25f - 1.0f) *
                       ((float)((n + 2 * k) % 8) * 0.25f - 0.75f);
            float got = __uint_as_float(d[n]);
            if (!(fabsf(got - ref) <= 1e-2f)) bad++;
        }
        if (bad) atomicAdd(&perr, bad);
    }
    __syncthreads();
    if (tid == 0) { g_tc_ok = (perr == 0) ? 1 : 0; MBAR_INVAL(cb + 8); }
    __syncthreads();
    if (wid == 0) tcgen05_dealloc(tmem, 64);
#else
    if (threadIdx.x == 0) g_tc_ok = 0;
#endif
}

// =====================================================================
// Fallback: mma.sync tf32 GEMM core — exact R13 (723 us, known-passing)
// =====================================================================
#define BM 128
#define BN 64
#define BK 16
#define ASTR 20
#define BSTR 72

__device__ __forceinline__ void mma8(float c[4], const uint32_t a[4], const uint32_t b[2]) {
    asm volatile(
        "mma.sync.aligned.m16n8k8.row.col.f32.tf32.tf32.f32 "
        "{%0,%1,%2,%3}, {%4,%5,%6,%7}, {%8,%9}, {%0,%1,%2,%3};"
        : "+f"(c[0]), "+f"(c[1]), "+f"(c[2]), "+f"(c[3])
        : "r"(a[0]), "r"(a[1]), "r"(a[2]), "r"(a[3]), "r"(b[0]), "r"(b[1]));
}

template<bool FUSED>
__device__ __forceinline__ void mma_gemm(
    const float* __restrict__ A, int lda,
    const int* __restrict__ rowmap, int row_off, int Mrem,
    const float* __restrict__ B0, const float* __restrict__ B1, int ldb, int nbase,
    float* __restrict__ C, int ldc, int K)
{
    __shared__ uint32_t As[2][BM * ASTR];
    __shared__ uint32_t Bs[2][BK * BSTR];

    int tid  = threadIdx.x;
    int warp = tid >> 5, lane = tid & 31;
    int wm = warp >> 1, wn = warp & 1;
    int g  = lane >> 2, t0 = lane & 3;
    int mb = wm * 32,  nb = wn * 32;

    int ar = tid >> 1;
    int ac = (tid & 1) * 8;
    bool aval = ar < Mrem;
    const float* aptr = A;
    if (aval) {
        int r = rowmap ? rowmap[row_off + ar] : (row_off + ar);
        aptr = A + (size_t)r * lda + ac;
    }

    int bk  = tid >> 4;
    int bn4 = (tid & 15) * 4;
    const float* bptr;
    if (FUSED) {
        int q = bn4 >> 4, within = bn4 & 15;
        const float* Bsel = (q & 1) ? B1 : B0;
        bptr = Bsel + (size_t)bk * ldb + nbase + ((q >> 1) << 4) + within;
    } else {
        bptr = B0 + (size_t)bk * ldb + nbase + bn4;
    }

    float4 av0, av1, bv;
    const float4 z4 = make_float4(0.f, 0.f, 0.f, 0.f);

    float acc[2][4][4];
    #pragma unroll
    for (int i = 0; i < 2; i++)
        #pragma unroll
        for (int j = 0; j < 4; j++)
            #pragma unroll
            for (int l = 0; l < 4; l++) acc[i][j][l] = 0.f;

    const int niter = K / BK;

    av0 = aval ? *(const float4*)(aptr)     : z4;
    av1 = aval ? *(const float4*)(aptr + 4) : z4;
    bv  = *(const float4*)(bptr);
    {
        uint32_t* d = &As[0][ar * ASTR + ac];
        d[0]=f2tf(av0.x); d[1]=f2tf(av0.y); d[2]=f2tf(av0.z); d[3]=f2tf(av0.w);
        d[4]=f2tf(av1.x); d[5]=f2tf(av1.y); d[6]=f2tf(av1.z); d[7]=f2tf(av1.w);
        uint32_t* e2 = &Bs[0][bk * BSTR + bn4];
        e2[0]=f2tf(bv.x); e2[1]=f2tf(bv.y); e2[2]=f2tf(bv.z); e2[3]=f2tf(bv.w);
    }
    __syncthreads();
    if (niter > 1) {
        av0 = aval ? *(const float4*)(aptr + BK)     : z4;
        av1 = aval ? *(const float4*)(aptr + BK + 4) : z4;
        bv  = *(const float4*)(bptr + (size_t)BK * ldb);
    }

    int s = 0;
    for (int it = 0; it < niter; it++) {
        #pragma unroll
        for (int ks = 0; ks < 2; ks++) {
            int kb = ks * 8;
            uint32_t afr[2][4];
            #pragma unroll
            for (int mt = 0; mt < 2; mt++) {
                int r = mb + mt * 16 + g;
                afr[mt][0] = As[s][r * ASTR + kb + t0];
                afr[mt][1] = As[s][(r + 8) * ASTR + kb + t0];
                afr[mt][2] = As[s][r * ASTR + kb + t0 + 4];
                afr[mt][3] = As[s][(r + 8) * ASTR + kb + t0 + 4];
            }
            #pragma unroll
            for (int nt = 0; nt < 4; nt++) {
                uint32_t bfr[2];
                bfr[0] = Bs[s][(kb + t0) * BSTR + nb + nt * 8 + g];
                bfr[1] = Bs[s][(kb + t0 + 4) * BSTR + nb + nt * 8 + g];
                mma8(acc[0][nt], afr[0], bfr);
                mma8(acc[1][nt], afr[1], bfr);
            }
        }
        if (it + 1 < niter) {
            uint32_t* d = &As[s ^ 1][ar * ASTR + ac];
            d[0]=f2tf(av0.x); d[1]=f2tf(av0.y); d[2]=f2tf(av0.z); d[3]=f2tf(av0.w);
            d[4]=f2tf(av1.x); d[5]=f2tf(av1.y); d[6]=f2tf(av1.z); d[7]=f2tf(av1.w);
            uint32_t* e2 = &Bs[s ^ 1][bk * BSTR + bn4];
            e2[0]=f2tf(bv.x); e2[1]=f2tf(bv.y); e2[2]=f2tf(bv.z); e2[3]=f2tf(bv.w);
            __syncthreads();
            s ^= 1;
            if (it + 2 < niter) {
                int k0 = (it + 2) * BK;
                av0 = aval ? *(const float4*)(aptr + k0)     : z4;
                av1 = aval ? *(const float4*)(aptr + k0 + 4) : z4;
                bv  = *(const float4*)(bptr + (size_t)k0 * ldb);
            }
        }
    }

    #pragma unroll
    for (int mt = 0; mt < 2; mt++) {
        int r0 = mb + mt * 16 + g;
        int r1 = r0 + 8;
        if (FUSED) {
            #pragma unroll
            for (int nt = 0; nt < 2; nt++) {
                int c = nbase + (wn << 4) + nt * 8 + 2 * t0;
                float a00 = silu_mul(acc[mt][nt][0], acc[mt][nt + 2][0]);
                float a01 = silu_mul(acc[mt][nt][1], acc[mt][nt + 2][1]);
                float a10 = silu_mul(acc[mt][nt][2], acc[mt][nt + 2][2]);
                float a11 = silu_mul(acc[mt][nt][3], acc[mt][nt + 2][3]);
                if (r0 < Mrem) *(float2*)(C + (size_t)r0 * ldc + c) = make_float2(a00, a01);
                if (r1 < Mrem) *(float2*)(C + (size_t)r1 * ldc + c) = make_float2(a10, a11);
            }
        } else {
            #pragma unroll
            for (int nt = 0; nt < 4; nt++) {
                int c = nbase + nb + nt * 8 + 2 * t0;
                if (r0 < Mrem)
                    *(float2*)(C + (size_t)r0 * ldc + c) = make_float2(acc[mt][nt][0], acc[mt][nt][1]);
                if (r1 < Mrem)
                    *(float2*)(C + (size_t)r1 * ldc + c) = make_float2(acc[mt][nt][2], acc[mt][nt][3]);
            }
        }
    }
}

// ---------------- GEMM wrappers: runtime dispatch on g_tc_ok ----------------
__global__ void __launch_bounds__(256, 2)
k_routed_gateup(const float* __restrict__ x,
                const float* __restrict__ wg,
                const float* __restrict__ wu) {
    int e   = blockIdx.z;
    int seg = g_offsets[e];
    int ne  = g_offsets[e + 1] - seg;
    int mt  = blockIdx.y * 128;
    if (mt >= ne) return;
    int nbase = blockIdx.x * 32;
#if USE_TCGEN05
    if (g_tc_ok) {
        tc_gemm<true>(x, H, g_pair_token, seg + mt, ne - mt,
                      wg + (size_t)e * H * IW, wu + (size_t)e * H * IW, IW, nbase,
                      g_act + (size_t)(seg + mt) * IW, IW, H);
        return;
    }
#endif
    mma_gemm<true>(x, H, g_pair_token, seg + mt, ne - mt,
                   wg + (size_t)e * H * IW, wu + (size_t)e * H * IW, IW, nbase,
                   g_act + (size_t)(seg + mt) * IW, IW, H);
}

__global__ void __launch_bounds__(256, 2)
k_routed_down(const float* __restrict__ wd) {
    int e   = blockIdx.z;
    int seg = g_offsets[e];
    int ne  = g_offsets[e + 1] - seg;
    int mt  = blockIdx.y * 128;
    if (mt >= ne) return;
    int nbase = blockIdx.x * 64;
#if USE_TCGEN05
    if (g_tc_ok) {
        tc_gemm<false>(g_act, IW, nullptr, seg + mt, ne - mt,
                       wd + (size_t)e * IW * H, nullptr, H, nbase,
                       g_down + (size_t)(seg + mt) * 1024, 1024, IW);
        return;
    }
#endif
    mma_gemm<false>(g_act, IW, nullptr, seg + mt, ne - mt,
                    wd + (size_t)e * IW * H, nullptr, H, nbase,
                    g_down + (size_t)(seg + mt) * 1024, 1024, IW);
}

__global__ void __launch_bounds__(256, 2)
k_shared_gateup(const float* __restrict__ x,
                const float* __restrict__ sg,
                const float* __restrict__ su) {
    int mt = blockIdx.y * 128;
    int nbase = blockIdx.x * 32;
#if USE_TCGEN05
    if (g_tc_ok) {
        tc_gemm<true>(x, H, nullptr, mt, T - mt,
                      sg, su, ISH, nbase,
                      g_sact + (size_t)mt * ISH, ISH, H);
        return;
    }
#endif
    mma_gemm<true>(x, H, nullptr, mt, T - mt,
                   sg, su, ISH, nbase,
                   g_sact + (size_t)mt * ISH, ISH, H);
}

__global__ void __launch_bounds__(256, 2)
k_shared_down(const float* __restrict__ sd, float* __restrict__ out) {
    int mt = blockIdx.y * 128;
    int nbase = blockIdx.x * 64;
#if USE_TCGEN05
    if (g_tc_ok) {
        tc_gemm<false>(g_sact, ISH, nullptr, mt, T - mt,
                       sd, nullptr, H, nbase,
                       out + (size_t)mt * H, H, ISH);
        return;
    }
#endif
    mma_gemm<false>(g_sact, ISH, nullptr, mt, T - mt,
                    sd, nullptr, H, nbase,
                    out + (size_t)mt * H, H, ISH);
}

// out += w1*down[p1] + w2*down[p2]  (one thread per element -> deterministic)
__global__ void k_combine(float* __restrict__ out) {
    int idx = blockIdx.x * blockDim.x + threadIdx.x;
    if (idx >= T * H) return;
    int t = idx >> 10, h = idx & 1023;
    float r = out[idx];
    r += g_topk_w[t * 2]     * g_down[(size_t)g_pos_of[t * 2]     * 1024 + h];
    r += g_topk_w[t * 2 + 1] * g_down[(size_t)g_pos_of[t * 2 + 1] * 1024 + h];
    out[idx] = r;
}

// ---------------- launch ----------------
extern "C" void kernel_launch(void* const* d_in, const int* in_sizes, int n_in,
                              void* d_out, int out_size) {
    const float* x  = (const float*)d_in[0];   // [T, H]
    const float* rw = (const float*)d_in[1];   // [E, H]
    const float* wg = (const float*)d_in[2];   // [E, H, I]
    const float* wu = (const float*)d_in[3];   // [E, H, I]
    const float* wd = (const float*)d_in[4];   // [E, I, H]
    const float* sg = (const float*)d_in[5];   // [H, IS]
    const float* su = (const float*)d_in[6];   // [H, IS]
    const float* sd = (const float*)d_in[7];   // [IS, H]
    float* out = (float*)d_out;                // [T, H]

    cudaFuncSetAttribute(k_routed_gateup, cudaFuncAttributeMaxDynamicSharedMemorySize, SMEM_BYTES);
    cudaFuncSetAttribute(k_routed_down,   cudaFuncAttributeMaxDynamicSharedMemorySize, SMEM_BYTES);
    cudaFuncSetAttribute(k_shared_gateup, cudaFuncAttributeMaxDynamicSharedMemorySize, SMEM_BYTES);
    cudaFuncSetAttribute(k_shared_down,   cudaFuncAttributeMaxDynamicSharedMemorySize, SMEM_BYTES);

    // probe tcgen05 correctness (writes g_tc_ok), then routing
    k_tc_probe<<<1, 256>>>();
    k_init<<<1, 32>>>();
    k_router<<<T, 128>>>(x, rw);
    k_scan<<<1, 32>>>();
    k_scatter<<<16, 256>>>();

    // shared expert (writes out with "=")
    k_shared_gateup<<<dim3(ISH / 32, T / 128, 1), 256, SMEM_BYTES>>>(x, sg, su);
    k_shared_down<<<dim3(H / 64, T / 128, 1), 256, SMEM_BYTES>>>(sd, out);

    // routed experts (expert-grouped; y sized for worst-case imbalance)
    k_routed_gateup<<<dim3(IW / 32, P / 128, E), 256, SMEM_BYTES>>>(x, wg, wu);
    k_routed_down<<<dim3(H / 64, P / 128, E), 256, SMEM_BYTES>>>(wd);

    // final combine
    k_combine<<<(T * H + 255) / 256, 256>>>(out);
}